// round 1
// baseline (speedup 1.0000x reference)
#include <cuda_runtime.h>

// Problem constants
#define B_DIM 32
#define C_DIM 512
#define N_DIM 1024   // H*W = 32*32
#define D_DIM 64     // head dim
#define R_DIM 128    // distinct projection rows per batch (period of broadcast)

// Scratch (device globals — allocation-free)
__device__ float g_wv[C_DIM * D_DIM];            // head-averaged V weights [c][d]
__device__ float g_bv[D_DIM];                    // head-averaged V bias
__device__ float g_v[B_DIM * N_DIM * D_DIM];     // v[b][n][d]  == A2[b][128][512] row-major

// ---------------------------------------------------------------------------
// K0: fold the head-mean into a single 512x64 weight + 64 bias
// Wv[c,d] = (1/8) sum_h W_qkv[c, 1024 + h*64 + d]
// ---------------------------------------------------------------------------
__global__ void prep_kernel(const float* __restrict__ Wqkv,
                            const float* __restrict__ bqkv) {
    int idx = blockIdx.x * blockDim.x + threadIdx.x;
    if (idx < C_DIM * D_DIM) {
        int c = idx >> 6, d = idx & 63;
        const float* p = Wqkv + (size_t)c * 1536 + 1024 + d;
        float s = 0.f;
        #pragma unroll
        for (int h = 0; h < 8; ++h) s += p[h * 64];
        g_wv[idx] = s * 0.125f;
    }
    if (idx < D_DIM) {
        float s = 0.f;
        #pragma unroll
        for (int h = 0; h < 8; ++h) s += bqkv[1024 + h * 64 + idx];
        g_bv[idx] = s * 0.125f;
    }
}

// ---------------------------------------------------------------------------
// K1: v[b,n,d] = sum_c x[b,c,n] * Wv[c,d] + bv[d]
// Per-batch GEMM: X^T (1024x512) @ Wv (512x64).
// Block: 128(n) x 64(d) tile, 256 threads, thread tile 8(n) x 4(d), KT=32.
// grid = (N/128, B) = (8, 32)
// ---------------------------------------------------------------------------
#define K1_KT 32
__global__ void __launch_bounds__(256) gemm1_kernel(const float* __restrict__ x) {
    __shared__ float As[K1_KT][128];   // x[k][n]   (naturally k-row, n-contiguous)
    __shared__ float Bs[K1_KT][64];    // wv[k][d]

    const int b   = blockIdx.y;
    const int n0  = blockIdx.x * 128;
    const int tid = threadIdx.x;
    const int tr  = tid & 15;          // n-group (16)
    const int tc  = tid >> 4;          // d-group (16)

    const float* xb = x + (size_t)b * C_DIM * N_DIM;
    float acc[8][4] = {};

    for (int c0 = 0; c0 < C_DIM; c0 += K1_KT) {
        // Load As: 32 rows x 128 floats = 1024 float4, 4 per thread (coalesced)
        #pragma unroll
        for (int it = 0; it < 4; ++it) {
            int f = tid + it * 256;
            int k = f >> 5, nq = f & 31;
            float4 val = *(const float4*)(xb + (size_t)(c0 + k) * N_DIM + n0 + nq * 4);
            *(float4*)(&As[k][nq * 4]) = val;
        }
        // Load Bs: 32 x 64 = 512 float4, 2 per thread
        #pragma unroll
        for (int it = 0; it < 2; ++it) {
            int f = tid + it * 256;
            int k = f >> 4, dq = f & 15;
            *(float4*)(&Bs[k][dq * 4]) =
                *(const float4*)(g_wv + (size_t)(c0 + k) * D_DIM + dq * 4);
        }
        __syncthreads();

        #pragma unroll
        for (int k = 0; k < K1_KT; ++k) {
            float a[8], bb[4];
            *(float4*)(a)     = *(const float4*)(&As[k][tr * 8]);
            *(float4*)(a + 4) = *(const float4*)(&As[k][tr * 8 + 4]);
            *(float4*)(bb)    = *(const float4*)(&Bs[k][tc * 4]);
            #pragma unroll
            for (int i = 0; i < 8; ++i)
                #pragma unroll
                for (int j = 0; j < 4; ++j)
                    acc[i][j] = fmaf(a[i], bb[j], acc[i][j]);
        }
        __syncthreads();
    }

    // Writeout with bias
    float bias[4];
    *(float4*)bias = *(const float4*)(g_bv + tc * 4);
    float* vb = g_v + (size_t)b * N_DIM * D_DIM;
    #pragma unroll
    for (int i = 0; i < 8; ++i) {
        int n = n0 + tr * 8 + i;
        float4 o = make_float4(acc[i][0] + bias[0], acc[i][1] + bias[1],
                               acc[i][2] + bias[2], acc[i][3] + bias[3]);
        *(float4*)(vb + (size_t)n * D_DIM + tc * 4) = o;
    }
}

// ---------------------------------------------------------------------------
// K2: Y[b] (128x512) = A2[b] (128x512) @ W_proj (512x512) + b_proj,
//     where A2[b] = g_v[b] reinterpreted (reshape is free).
// Output broadcast: out[b, c2, m*128 + r] = Y[b, r, c2] for m = 0..7.
// Block: 128(r) x 64(c2) tile, 256 threads, thread tile 8(r) x 4(c2), KT=32.
// grid = (512/64, B) = (8, 32)
// ---------------------------------------------------------------------------
#define K2_KT 32
__global__ void __launch_bounds__(256) gemm2_kernel(const float* __restrict__ Wp,
                                                    const float* __restrict__ bp,
                                                    float* __restrict__ out) {
    __shared__ float As[K2_KT][132];   // A2^T [k][r], padded row (132*4B = 16B-aligned)
    __shared__ float Bs[K2_KT][64];    // Wp[k][c2]

    const int b    = blockIdx.y;
    const int c2_0 = blockIdx.x * 64;
    const int tid  = threadIdx.x;
    const int tr   = tid & 15;         // r-group (16)
    const int tc   = tid >> 4;         // c2-group (16)

    const float* ab = g_v + (size_t)b * R_DIM * C_DIM;   // [r][c], 128x512
    float acc[8][4] = {};

    for (int c0 = 0; c0 < C_DIM; c0 += K2_KT) {
        // Load A transposed: 128 rows x 32 k = 1024 float4, 4 per thread
        #pragma unroll
        for (int it = 0; it < 4; ++it) {
            int f = tid + it * 256;
            int r = f >> 3, kq = f & 7;
            float4 val = *(const float4*)(ab + (size_t)r * C_DIM + c0 + kq * 4);
            As[kq * 4 + 0][r] = val.x;
            As[kq * 4 + 1][r] = val.y;
            As[kq * 4 + 2][r] = val.z;
            As[kq * 4 + 3][r] = val.w;
        }
        // Load B: 32 rows x 64 floats
        #pragma unroll
        for (int it = 0; it < 2; ++it) {
            int f = tid + it * 256;
            int k = f >> 4, cq = f & 15;
            *(float4*)(&Bs[k][cq * 4]) =
                *(const float4*)(Wp + (size_t)(c0 + k) * C_DIM + c2_0 + cq * 4);
        }
        __syncthreads();

        #pragma unroll
        for (int k = 0; k < K2_KT; ++k) {
            float a[8], bb[4];
            *(float4*)(a)     = *(const float4*)(&As[k][tr * 8]);
            *(float4*)(a + 4) = *(const float4*)(&As[k][tr * 8 + 4]);
            *(float4*)(bb)    = *(const float4*)(&Bs[k][tc * 4]);
            #pragma unroll
            for (int i = 0; i < 8; ++i)
                #pragma unroll
                for (int j = 0; j < 4; ++j)
                    acc[i][j] = fmaf(a[i], bb[j], acc[i][j]);
        }
        __syncthreads();
    }

    float bias[4];
    *(float4*)bias = *(const float4*)(bp + c2_0 + tc * 4);

    // out[b, c2, m*128 + r]; float4 along r, broadcast over m = 0..7
    float* ob = out + (size_t)b * C_DIM * N_DIM;
    #pragma unroll
    for (int j = 0; j < 4; ++j) {
        int c2 = c2_0 + tc * 4 + j;
        float* oc = ob + (size_t)c2 * N_DIM;
        #pragma unroll
        for (int i2 = 0; i2 < 2; ++i2) {
            float4 o;
            o.x = acc[i2 * 4 + 0][j] + bias[j];
            o.y = acc[i2 * 4 + 1][j] + bias[j];
            o.z = acc[i2 * 4 + 2][j] + bias[j];
            o.w = acc[i2 * 4 + 3][j] + bias[j];
            int r = tr * 8 + i2 * 4;
            #pragma unroll
            for (int m = 0; m < 8; ++m)
                *(float4*)(oc + m * R_DIM + r) = o;
        }
    }
}

// ---------------------------------------------------------------------------
extern "C" void kernel_launch(void* const* d_in, const int* in_sizes, int n_in,
                              void* d_out, int out_size) {
    const float* x    = (const float*)d_in[0];   // (32, 512, 32, 32)
    const float* Wqkv = (const float*)d_in[1];   // (512, 1536)
    const float* bqkv = (const float*)d_in[2];   // (1536,)
    const float* Wp   = (const float*)d_in[3];   // (512, 512)
    const float* bp   = (const float*)d_in[4];   // (512,)
    float* out = (float*)d_out;                  // (32, 512, 32, 32)

    prep_kernel<<<(C_DIM * D_DIM + 255) / 256, 256>>>(Wqkv, bqkv);
    gemm1_kernel<<<dim3(N_DIM / 128, B_DIM), 256>>>(x);
    gemm2_kernel<<<dim3(C_DIM / 64, B_DIM), 256>>>(Wp, bp, out);
}

// round 3
// speedup vs baseline: 2.0737x; 2.0737x over previous
#include <cuda_runtime.h>
#include <cuda_bf16.h>
#include <cstdint>

#define B_DIM 32
#define C_DIM 512
#define N_DIM 1024   // H*W

// ---------------- device scratch (allocation-free) --------------------------
__device__ __align__(16) unsigned short g_wvh[64 * 512];    // Wv^T hi  [d][c]
__device__ __align__(16) unsigned short g_wvl[64 * 512];    // Wv^T lo
__device__ __align__(16) unsigned short g_wph[512 * 512];   // Wp^T hi  [c2][c]
__device__ __align__(16) unsigned short g_wpl[512 * 512];   // Wp^T lo
__device__ float g_bv[64];
__device__ __align__(16) unsigned g_vh[B_DIM * 1024 * 32];  // v hi bf16 pairs [b][n][d/2]
__device__ __align__(16) unsigned g_vl[B_DIM * 1024 * 32];  // v lo

// ---------------- helpers ----------------------------------------------------
__device__ __forceinline__ unsigned smem_u32(const void* p) {
    unsigned a;
    asm("{ .reg .u64 t; cvta.to.shared.u64 t, %1; cvt.u32.u64 %0, t; }" : "=r"(a) : "l"(p));
    return a;
}
__device__ __forceinline__ void ldm_x4(unsigned* d, unsigned addr) {
    asm volatile("ldmatrix.sync.aligned.m8n8.x4.shared.b16 {%0,%1,%2,%3}, [%4];"
                 : "=r"(d[0]), "=r"(d[1]), "=r"(d[2]), "=r"(d[3]) : "r"(addr));
}
__device__ __forceinline__ void ldm_x2(unsigned* d, unsigned addr) {
    asm volatile("ldmatrix.sync.aligned.m8n8.x2.shared.b16 {%0,%1}, [%2];"
                 : "=r"(d[0]), "=r"(d[1]) : "r"(addr));
}
__device__ __forceinline__ void mma_bf16(float* c, const unsigned* a, const unsigned* b) {
    asm volatile(
        "mma.sync.aligned.m16n8k16.row.col.f32.bf16.bf16.f32 "
        "{%0,%1,%2,%3}, {%4,%5,%6,%7}, {%8,%9}, {%0,%1,%2,%3};"
        : "+f"(c[0]), "+f"(c[1]), "+f"(c[2]), "+f"(c[3])
        : "r"(a[0]), "r"(a[1]), "r"(a[2]), "r"(a[3]), "r"(b[0]), "r"(b[1]));
}
// split (f0, f1) into hi/lo bf16x2 (lo half of word = f0)
__device__ __forceinline__ void cvt_split_pair(float f0, float f1, unsigned& h, unsigned& l) {
    asm("cvt.rn.bf16x2.f32 %0, %1, %2;" : "=r"(h) : "f"(f1), "f"(f0));
    float r0 = f0 - __uint_as_float(h << 16);
    float r1 = f1 - __uint_as_float(h & 0xffff0000u);
    asm("cvt.rn.bf16x2.f32 %0, %1, %2;" : "=r"(l) : "f"(r1), "f"(r0));
}

// smem layout (bytes): Ah[128][40]h @0 (10240) | Al @10240 | Bh[64][40]h @20480 (5120) | Bl @25600
// union with Cs[64][132] floats (33792 B) for gemm2 epilogue
#define OFF_AL 10240
#define OFF_B  20480
#define OFF_BL 5120
#define SMEM_BYTES 33792

// ---------------------------------------------------------------------------
// prep: Wv^T split + bias  (Wv[c][d] = mean_h Wqkv[c][1024 + h*64 + d])
// ---------------------------------------------------------------------------
__global__ void prep_wv(const float* __restrict__ Wqkv, const float* __restrict__ bqkv) {
    int idx = blockIdx.x * blockDim.x + threadIdx.x;   // 32768
    int c = idx & 511, d = idx >> 9;
    const float* p = Wqkv + (size_t)c * 1536 + 1024 + d;
    float s = 0.f;
    #pragma unroll
    for (int h = 0; h < 8; ++h) s += p[h * 64];
    s *= 0.125f;
    __nv_bfloat16 hi = __float2bfloat16(s);
    __nv_bfloat16 lo = __float2bfloat16(s - __bfloat162float(hi));
    g_wvh[d * 512 + c] = *(unsigned short*)&hi;
    g_wvl[d * 512 + c] = *(unsigned short*)&lo;
    if (idx < 64) {
        float t = 0.f;
        #pragma unroll
        for (int h = 0; h < 8; ++h) t += bqkv[1024 + h * 64 + idx];
        g_bv[idx] = t * 0.125f;
    }
}

// prep: Wp^T split
__global__ void prep_wp(const float* __restrict__ Wp) {
    int idx = blockIdx.x * blockDim.x + threadIdx.x;   // 262144
    int c = idx & 511, c2 = idx >> 9;
    float s = Wp[(size_t)c * 512 + c2];
    __nv_bfloat16 hi = __float2bfloat16(s);
    __nv_bfloat16 lo = __float2bfloat16(s - __bfloat162float(hi));
    g_wph[c2 * 512 + c] = *(unsigned short*)&hi;
    g_wpl[c2 * 512 + c] = *(unsigned short*)&lo;
}

// ---------------------------------------------------------------------------
// GEMM1: v[b,n,d] = sum_c x[b,c,n] * Wv[c,d] + bv[d]; output split bf16 hi/lo
// block: 128 (n) x 64 (d); grid (8, 32)
// ---------------------------------------------------------------------------
__global__ void __launch_bounds__(256) gemm1_mma(const float* __restrict__ x) {
    __shared__ __align__(16) char smem_raw[SMEM_BYTES];
    const int tid = threadIdx.x, lane = tid & 31, wid = tid >> 5;
    const int mw = wid >> 1, nw = wid & 1;
    const int b = blockIdx.y, n0 = blockIdx.x * 128;
    const unsigned sb = smem_u32(smem_raw);

    // per-thread ldmatrix offsets
    const int j4 = lane >> 3, r8 = lane & 7, t16 = lane & 15;
    unsigned aoff[2], boff[4];
    #pragma unroll
    for (int mi = 0; mi < 2; ++mi)
        aoff[mi] = ((mw * 32 + mi * 16 + (j4 & 1) * 8 + r8) * 40 + (j4 >> 1) * 8) * 2;
    #pragma unroll
    for (int ni = 0; ni < 4; ++ni)
        boff[ni] = OFF_B + ((nw * 32 + ni * 8 + (t16 & 7)) * 40 + (t16 >> 3) * 8) * 2;

    float C[2][4][4] = {};
    const float* xb = x + (size_t)b * (C_DIM * N_DIM) + n0;

    for (int kc = 0; kc < 16; ++kc) {
        // A: x chunk, fp32 -> split bf16, transposed into [m][k]
        const float* xc = xb + (size_t)kc * 32 * N_DIM;
        #pragma unroll
        for (int i = 0; i < 8; ++i) {
            int p = tid + i * 256, m = p & 127, kp = p >> 7;
            float f0 = xc[(2 * kp) * N_DIM + m];
            float f1 = xc[(2 * kp + 1) * N_DIM + m];
            unsigned h, l;
            cvt_split_pair(f0, f1, h, l);
            unsigned off = m * 80 + kp * 4;
            *(unsigned*)(smem_raw + off) = h;
            *(unsigned*)(smem_raw + OFF_AL + off) = l;
        }
        // B: straight copy of pre-split Wv^T
        {
            int d = tid >> 2, q = tid & 3;
            size_t s = (size_t)d * 512 + kc * 32 + q * 8;
            unsigned off = OFF_B + d * 80 + q * 16;
            *(uint4*)(smem_raw + off) = *(const uint4*)(g_wvh + s);
            *(uint4*)(smem_raw + off + OFF_BL) = *(const uint4*)(g_wvl + s);
        }
        __syncthreads();
        #pragma unroll
        for (int ks = 0; ks < 2; ++ks) {
            unsigned ah[2][4], al[2][4], bh[4][2], bl[4][2];
            #pragma unroll
            for (int mi = 0; mi < 2; ++mi) {
                ldm_x4(ah[mi], sb + aoff[mi] + ks * 32);
                ldm_x4(al[mi], sb + aoff[mi] + ks * 32 + OFF_AL);
            }
            #pragma unroll
            for (int ni = 0; ni < 4; ++ni) {
                ldm_x2(bh[ni], sb + boff[ni] + ks * 32);
                ldm_x2(bl[ni], sb + boff[ni] + ks * 32 + OFF_BL);
            }
            #pragma unroll
            for (int mi = 0; mi < 2; ++mi)
                #pragma unroll
                for (int ni = 0; ni < 4; ++ni) {
                    mma_bf16(C[mi][ni], ah[mi], bh[ni]);
                    mma_bf16(C[mi][ni], ah[mi], bl[ni]);
                    mma_bf16(C[mi][ni], al[mi], bh[ni]);
                }
        }
        __syncthreads();
    }

    // epilogue: add bias, re-split to bf16 hi/lo, store v
    const int gr = lane >> 2, gc2 = (lane & 3) * 2;
    #pragma unroll
    for (int mi = 0; mi < 2; ++mi) {
        int m = n0 + mw * 32 + mi * 16 + gr;
        unsigned base0 = (unsigned)(b * 1024 + m) * 32u;
        unsigned base1 = base0 + 8 * 32;
        #pragma unroll
        for (int ni = 0; ni < 4; ++ni) {
            int d = nw * 32 + ni * 8 + gc2;
            float bv0 = g_bv[d], bv1 = g_bv[d + 1];
            unsigned h, l;
            cvt_split_pair(C[mi][ni][0] + bv0, C[mi][ni][1] + bv1, h, l);
            g_vh[base0 + (d >> 1)] = h;
            g_vl[base0 + (d >> 1)] = l;
            cvt_split_pair(C[mi][ni][2] + bv0, C[mi][ni][3] + bv1, h, l);
            g_vh[base1 + (d >> 1)] = h;
            g_vl[base1 + (d >> 1)] = l;
        }
    }
}

// ---------------------------------------------------------------------------
// GEMM2: Y[b,r,c2] = sum_c vflat[b,r,c] * Wp[c,c2] + bp[c2]
//        out[b, c2, m*128 + r] = Y[b,r,c2], m = 0..7
// block: 128 (r) x 64 (c2); grid (8, 32)
// ---------------------------------------------------------------------------
__global__ void __launch_bounds__(256) gemm2_mma(const float* __restrict__ bp,
                                                 float* __restrict__ out) {
    __shared__ __align__(16) char smem_raw[SMEM_BYTES];
    const int tid = threadIdx.x, lane = tid & 31, wid = tid >> 5;
    const int mw = wid >> 1, nw = wid & 1;
    const int b = blockIdx.y, c20 = blockIdx.x * 64;
    const unsigned sb = smem_u32(smem_raw);

    const int j4 = lane >> 3, r8 = lane & 7, t16 = lane & 15;
    unsigned aoff[2], boff[4];
    #pragma unroll
    for (int mi = 0; mi < 2; ++mi)
        aoff[mi] = ((mw * 32 + mi * 16 + (j4 & 1) * 8 + r8) * 40 + (j4 >> 1) * 8) * 2;
    #pragma unroll
    for (int ni = 0; ni < 4; ++ni)
        boff[ni] = OFF_B + ((nw * 32 + ni * 8 + (t16 & 7)) * 40 + (t16 >> 3) * 8) * 2;

    float C[2][4][4] = {};
    const unsigned short* vhb = (const unsigned short*)g_vh + (size_t)b * 65536;
    const unsigned short* vlb = (const unsigned short*)g_vl + (size_t)b * 65536;

    for (int kc = 0; kc < 16; ++kc) {
        // A: straight copy of pre-split v rows [r][c]
        #pragma unroll
        for (int i = 0; i < 2; ++i) {
            int p = tid + i * 256, r = p >> 2, q = p & 3;
            size_t s = (size_t)r * 512 + kc * 32 + q * 8;
            unsigned off = r * 80 + q * 16;
            *(uint4*)(smem_raw + off) = *(const uint4*)(vhb + s);
            *(uint4*)(smem_raw + OFF_AL + off) = *(const uint4*)(vlb + s);
        }
        // B: straight copy of pre-split Wp^T rows [c2][c]
        {
            int d = tid >> 2, q = tid & 3;
            size_t s = (size_t)(c20 + d) * 512 + kc * 32 + q * 8;
            unsigned off = OFF_B + d * 80 + q * 16;
            *(uint4*)(smem_raw + off) = *(const uint4*)(g_wph + s);
            *(uint4*)(smem_raw + off + OFF_BL) = *(const uint4*)(g_wpl + s);
        }
        __syncthreads();
        #pragma unroll
        for (int ks = 0; ks < 2; ++ks) {
            unsigned ah[2][4], al[2][4], bh[4][2], bl[4][2];
            #pragma unroll
            for (int mi = 0; mi < 2; ++mi) {
                ldm_x4(ah[mi], sb + aoff[mi] + ks * 32);
                ldm_x4(al[mi], sb + aoff[mi] + ks * 32 + OFF_AL);
            }
            #pragma unroll
            for (int ni = 0; ni < 4; ++ni) {
                ldm_x2(bh[ni], sb + boff[ni] + ks * 32);
                ldm_x2(bl[ni], sb + boff[ni] + ks * 32 + OFF_BL);
            }
            #pragma unroll
            for (int mi = 0; mi < 2; ++mi)
                #pragma unroll
                for (int ni = 0; ni < 4; ++ni) {
                    mma_bf16(C[mi][ni], ah[mi], bh[ni]);
                    mma_bf16(C[mi][ni], ah[mi], bl[ni]);
                    mma_bf16(C[mi][ni], al[mi], bh[ni]);
                }
        }
        __syncthreads();
    }

    // epilogue: stage to smem [c2][r] with bias, then coalesced broadcast x8
    float* Cs = (float*)smem_raw;      // [64][132]
    const int gr = lane >> 2, gc2 = (lane & 3) * 2;
    #pragma unroll
    for (int mi = 0; mi < 2; ++mi) {
        int r = mw * 32 + mi * 16 + gr;
        #pragma unroll
        for (int ni = 0; ni < 4; ++ni) {
            int c2l = nw * 32 + ni * 8 + gc2;
            float b0 = __ldg(bp + c20 + c2l), b1 = __ldg(bp + c20 + c2l + 1);
            Cs[c2l * 132 + r]           = C[mi][ni][0] + b0;
            Cs[(c2l + 1) * 132 + r]     = C[mi][ni][1] + b1;
            Cs[c2l * 132 + r + 8]       = C[mi][ni][2] + b0;
            Cs[(c2l + 1) * 132 + r + 8] = C[mi][ni][3] + b1;
        }
    }
    __syncthreads();

    float* ob = out + (size_t)b * (C_DIM * N_DIM) + (size_t)c20 * N_DIM;
    const int f4 = tid & 31, sub = tid >> 5;
    #pragma unroll 4
    for (int i = 0; i < 64; ++i) {
        int rowid = i * 8 + sub;
        int c2l = rowid >> 3, mrep = rowid & 7;
        float4 v = *(float4*)&Cs[c2l * 132 + f4 * 4];
        *(float4*)(ob + (size_t)c2l * N_DIM + mrep * 128 + f4 * 4) = v;
    }
}

// ---------------------------------------------------------------------------
extern "C" void kernel_launch(void* const* d_in, const int* in_sizes, int n_in,
                              void* d_out, int out_size) {
    const float* x    = (const float*)d_in[0];
    const float* Wqkv = (const float*)d_in[1];
    const float* bqkv = (const float*)d_in[2];
    const float* Wp   = (const float*)d_in[3];
    const float* bp   = (const float*)d_in[4];
    float* out = (float*)d_out;

    prep_wv<<<128, 256>>>(Wqkv, bqkv);
    prep_wp<<<1024, 256>>>(Wp);
    gemm1_mma<<<dim3(8, B_DIM), 256>>>(x);
    gemm2_mma<<<dim3(8, B_DIM), 256>>>(bp, out);
}

// round 4
// speedup vs baseline: 2.6369x; 1.2716x over previous
#include <cuda_runtime.h>
#include <cuda_bf16.h>
#include <cstdint>

#define B_DIM 32
#define C_DIM 512
#define N_DIM 1024   // H*W

// ---------------- device scratch (allocation-free) --------------------------
__device__ __align__(16) unsigned short g_wvh[64 * 512];    // Wv^T hi  [d][c]
__device__ __align__(16) unsigned short g_wvl[64 * 512];    // Wv^T lo
__device__ __align__(16) unsigned short g_wph[512 * 512];   // Wp^T hi  [c2][c]
__device__ __align__(16) unsigned short g_wpl[512 * 512];   // Wp^T lo
__device__ float g_bv[64];
__device__ __align__(16) unsigned g_vh[B_DIM * 1024 * 32];  // v hi bf16 pairs [b][n][d/2]
__device__ __align__(16) unsigned g_vl[B_DIM * 1024 * 32];  // v lo

// ---------------- helpers ----------------------------------------------------
__device__ __forceinline__ unsigned smem_u32(const void* p) {
    unsigned a;
    asm("{ .reg .u64 t; cvta.to.shared.u64 t, %1; cvt.u32.u64 %0, t; }" : "=r"(a) : "l"(p));
    return a;
}
__device__ __forceinline__ void ldm_x4(unsigned* d, unsigned addr) {
    asm volatile("ldmatrix.sync.aligned.m8n8.x4.shared.b16 {%0,%1,%2,%3}, [%4];"
                 : "=r"(d[0]), "=r"(d[1]), "=r"(d[2]), "=r"(d[3]) : "r"(addr));
}
__device__ __forceinline__ void mma_bf16(float* c, const unsigned* a, const unsigned* b) {
    asm volatile(
        "mma.sync.aligned.m16n8k16.row.col.f32.bf16.bf16.f32 "
        "{%0,%1,%2,%3}, {%4,%5,%6,%7}, {%8,%9}, {%0,%1,%2,%3};"
        : "+f"(c[0]), "+f"(c[1]), "+f"(c[2]), "+f"(c[3])
        : "r"(a[0]), "r"(a[1]), "r"(a[2]), "r"(a[3]), "r"(b[0]), "r"(b[1]));
}
__device__ __forceinline__ void cp16(unsigned dst, const void* src) {
    asm volatile("cp.async.cg.shared.global [%0], [%1], 16;" :: "r"(dst), "l"(src));
}
__device__ __forceinline__ void cp_commit() { asm volatile("cp.async.commit_group;" ::: "memory"); }
__device__ __forceinline__ void cp_wait0()  { asm volatile("cp.async.wait_group 0;" ::: "memory"); }

// split (f0, f1) into hi/lo bf16x2 (lo half of word = f0)
__device__ __forceinline__ void cvt_split_pair(float f0, float f1, unsigned& h, unsigned& l) {
    asm("cvt.rn.bf16x2.f32 %0, %1, %2;" : "=r"(h) : "f"(f1), "f"(f0));
    float r0 = f0 - __uint_as_float(h << 16);
    float r1 = f1 - __uint_as_float(h & 0xffff0000u);
    asm("cvt.rn.bf16x2.f32 %0, %1, %2;" : "=r"(l) : "f"(r1), "f"(r0));
}

// stage layout (bytes): Ah[128][40]h @0 | Al @10240 | Bh[64][40]h @20480 | Bl @25600
#define OFF_AL 10240
#define OFF_B  20480
#define OFF_BL 5120      // lo offset within B region
#define STG    30720     // per-stage stride
#define SMEM_DYN (2 * STG)   // 61440

// ---------------------------------------------------------------------------
// prep: Wv^T split + bias (coalesced: d-fast)
// ---------------------------------------------------------------------------
__global__ void prep_wv(const float* __restrict__ Wqkv, const float* __restrict__ bqkv) {
    int idx = blockIdx.x * blockDim.x + threadIdx.x;   // 32768
    int d = idx & 63, c = idx >> 6;
    const float* p = Wqkv + (size_t)c * 1536 + 1024 + d;
    float s = 0.f;
    #pragma unroll
    for (int h = 0; h < 8; ++h) s += p[h * 64];
    s *= 0.125f;
    __nv_bfloat16 hi = __float2bfloat16(s);
    __nv_bfloat16 lo = __float2bfloat16(s - __bfloat162float(hi));
    g_wvh[d * 512 + c] = *(unsigned short*)&hi;
    g_wvl[d * 512 + c] = *(unsigned short*)&lo;
    if (idx < 64) {
        float t = 0.f;
        #pragma unroll
        for (int h = 0; h < 8; ++h) t += bqkv[1024 + h * 64 + idx];
        g_bv[idx] = t * 0.125f;
    }
}

// prep: Wp^T split, tiled transpose (coalesced both sides)
__global__ void prep_wp(const float* __restrict__ Wp) {
    __shared__ float th[32][33], tl[32][33];
    int tx = threadIdx.x, ty = threadIdx.y;            // (32, 8)
    int c0 = blockIdx.x * 32, c20 = blockIdx.y * 32;
    #pragma unroll
    for (int i = 0; i < 4; ++i) {
        int c = c0 + ty + i * 8;
        float s = Wp[(size_t)c * 512 + c20 + tx];
        float hi = __bfloat162float(__float2bfloat16(s));
        th[ty + i * 8][tx] = hi;
        tl[ty + i * 8][tx] = s - hi;
    }
    __syncthreads();
    #pragma unroll
    for (int i = 0; i < 4; ++i) {
        int c2 = c20 + ty + i * 8;
        float hv = th[tx][ty + i * 8];
        float lv = tl[tx][ty + i * 8];
        __nv_bfloat16 hb = __float2bfloat16(hv);
        __nv_bfloat16 lb = __float2bfloat16(lv);
        g_wph[(size_t)c2 * 512 + c0 + tx] = *(unsigned short*)&hb;
        g_wpl[(size_t)c2 * 512 + c0 + tx] = *(unsigned short*)&lb;
    }
}

// ---------------- shared MMA stage (block 128x64, 8 warps, warp 32x32) -------
struct Frag { unsigned aoff[2]; unsigned boff[2]; };

__device__ __forceinline__ Frag make_frag(int lane, int wid) {
    Frag fr;
    const int mw = wid >> 1, nw = wid & 1;
    const int j4 = lane >> 3, r8 = lane & 7;
    #pragma unroll
    for (int mi = 0; mi < 2; ++mi)
        fr.aoff[mi] = ((mw * 32 + mi * 16 + (j4 & 1) * 8 + r8) * 40 + (j4 >> 1) * 8) * 2;
    const int g2 = (lane >> 4) & 1, c8 = (lane >> 3) & 1;
    #pragma unroll
    for (int j2 = 0; j2 < 2; ++j2)
        fr.boff[j2] = OFF_B + ((nw * 32 + j2 * 16 + g2 * 8 + r8) * 40 + c8 * 8) * 2;
    return fr;
}

__device__ __forceinline__ void mma_stage(unsigned base, const Frag& fr, float C[2][4][4]) {
    #pragma unroll
    for (int ks = 0; ks < 2; ++ks) {
        unsigned ah[2][4], al[2][4], bh[2][4], bl[2][4];
        #pragma unroll
        for (int mi = 0; mi < 2; ++mi) {
            ldm_x4(ah[mi], base + fr.aoff[mi] + ks * 32);
            ldm_x4(al[mi], base + fr.aoff[mi] + ks * 32 + OFF_AL);
        }
        #pragma unroll
        for (int j2 = 0; j2 < 2; ++j2) {
            ldm_x4(bh[j2], base + fr.boff[j2] + ks * 32);
            ldm_x4(bl[j2], base + fr.boff[j2] + ks * 32 + OFF_BL);
        }
        #pragma unroll
        for (int mi = 0; mi < 2; ++mi)
            #pragma unroll
            for (int ni = 0; ni < 4; ++ni) {
                const unsigned* bhp = &bh[ni >> 1][(ni & 1) * 2];
                const unsigned* blp = &bl[ni >> 1][(ni & 1) * 2];
                mma_bf16(C[mi][ni], ah[mi], bhp);
                mma_bf16(C[mi][ni], ah[mi], blp);
                mma_bf16(C[mi][ni], al[mi], bhp);
            }
    }
}

// ---------------------------------------------------------------------------
// GEMM1: v[b,n,d] = sum_c x[b,c,n]*Wv[c,d] + bv[d]; out split bf16; grid (8,32)
// ---------------------------------------------------------------------------
__global__ void __launch_bounds__(256) gemm1_mma(const float* __restrict__ x) {
    extern __shared__ char smem[];
    const int tid = threadIdx.x, lane = tid & 31, wid = tid >> 5;
    const int b = blockIdx.y, n0 = blockIdx.x * 128;
    const unsigned sb = smem_u32(smem);
    const Frag fr = make_frag(lane, wid);

    const int m_ld = tid & 127, kp0 = tid >> 7;   // A-load: kp = kp0 + 2i
    const int d_ld = tid >> 2, q_ld = tid & 3;    // B-copy
    const float* xb = x + (size_t)b * (C_DIM * N_DIM) + n0;

    float C[2][4][4] = {};
    float f[8][2];

    // prologue: chunk 0
    #pragma unroll
    for (int i = 0; i < 8; ++i) {
        int kp = kp0 + 2 * i;
        f[i][0] = xb[(size_t)(2 * kp) * N_DIM + m_ld];
        f[i][1] = xb[(size_t)(2 * kp + 1) * N_DIM + m_ld];
    }
    {   // B chunk 0 -> stage 0
        size_t s = (size_t)d_ld * 512 + q_ld * 8;
        unsigned doff = sb + OFF_B + d_ld * 80 + q_ld * 16;
        cp16(doff, g_wvh + s);
        cp16(doff + OFF_BL, g_wvl + s);
        cp_commit();
    }
    #pragma unroll
    for (int i = 0; i < 8; ++i) {
        int kp = kp0 + 2 * i;
        unsigned h, l;
        cvt_split_pair(f[i][0], f[i][1], h, l);
        unsigned off = m_ld * 80 + kp * 4;
        *(unsigned*)(smem + off) = h;
        *(unsigned*)(smem + OFF_AL + off) = l;
    }
    cp_wait0();
    __syncthreads();

    for (int kc = 0; kc < 16; ++kc) {
        const int st = kc & 1, nst = st ^ 1;
        if (kc < 15) {
            const float* xn = xb + (size_t)(kc + 1) * 32 * N_DIM;
            #pragma unroll
            for (int i = 0; i < 8; ++i) {
                int kp = kp0 + 2 * i;
                f[i][0] = xn[(size_t)(2 * kp) * N_DIM + m_ld];
                f[i][1] = xn[(size_t)(2 * kp + 1) * N_DIM + m_ld];
            }
            size_t s = (size_t)d_ld * 512 + (kc + 1) * 32 + q_ld * 8;
            unsigned doff = sb + nst * STG + OFF_B + d_ld * 80 + q_ld * 16;
            cp16(doff, g_wvh + s);
            cp16(doff + OFF_BL, g_wvl + s);
            cp_commit();
        }
        mma_stage(sb + st * STG, fr, C);
        if (kc < 15) {
            char* base = smem + nst * STG;
            #pragma unroll
            for (int i = 0; i < 8; ++i) {
                int kp = kp0 + 2 * i;
                unsigned h, l;
                cvt_split_pair(f[i][0], f[i][1], h, l);
                unsigned off = m_ld * 80 + kp * 4;
                *(unsigned*)(base + off) = h;
                *(unsigned*)(base + OFF_AL + off) = l;
            }
            cp_wait0();
        }
        __syncthreads();
    }

    // epilogue: add bias, re-split to bf16 hi/lo, store v
    const int mw = wid >> 1, nw = wid & 1;
    const int gr = lane >> 2, gc2 = (lane & 3) * 2;
    #pragma unroll
    for (int mi = 0; mi < 2; ++mi) {
        int m = n0 + mw * 32 + mi * 16 + gr;
        unsigned base0 = (unsigned)(b * 1024 + m) * 32u;
        unsigned base1 = base0 + 8 * 32;
        #pragma unroll
        for (int ni = 0; ni < 4; ++ni) {
            int d = nw * 32 + ni * 8 + gc2;
            float bv0 = g_bv[d], bv1 = g_bv[d + 1];
            unsigned h, l;
            cvt_split_pair(C[mi][ni][0] + bv0, C[mi][ni][1] + bv1, h, l);
            g_vh[base0 + (d >> 1)] = h;
            g_vl[base0 + (d >> 1)] = l;
            cvt_split_pair(C[mi][ni][2] + bv0, C[mi][ni][3] + bv1, h, l);
            g_vh[base1 + (d >> 1)] = h;
            g_vl[base1 + (d >> 1)] = l;
        }
    }
}

// ---------------------------------------------------------------------------
// GEMM2: Y[b,r,c2] = sum_c vflat[b,r,c]*Wp[c,c2] + bp[c2]
//        out[b, c2, m*128 + r], m = 0..7; grid (8,32)
// ---------------------------------------------------------------------------
__global__ void __launch_bounds__(256) gemm2_mma(const float* __restrict__ bp,
                                                 float* __restrict__ out) {
    extern __shared__ char smem[];
    const int tid = threadIdx.x, lane = tid & 31, wid = tid >> 5;
    const int b = blockIdx.y, c20 = blockIdx.x * 64;
    const unsigned sb = smem_u32(smem);
    const Frag fr = make_frag(lane, wid);

    const unsigned short* vhb = (const unsigned short*)g_vh + (size_t)b * 65536;
    const unsigned short* vlb = (const unsigned short*)g_vl + (size_t)b * 65536;
    const int d_ld = tid >> 2, q_ld = tid & 3;

    float C[2][4][4] = {};

    auto issue = [&](int kc, int st) {
        unsigned stb = sb + st * STG;
        // A: 128 rows x 2 splits, 2 iters
        #pragma unroll
        for (int i = 0; i < 2; ++i) {
            int p = tid + i * 256, r = p >> 2, q = p & 3;
            size_t s = (size_t)r * 512 + kc * 32 + q * 8;
            unsigned doff = stb + r * 80 + q * 16;
            cp16(doff, vhb + s);
            cp16(doff + OFF_AL, vlb + s);
        }
        // B: 64 rows x 2 splits
        {
            size_t s = (size_t)(c20 + d_ld) * 512 + kc * 32 + q_ld * 8;
            unsigned doff = stb + OFF_B + d_ld * 80 + q_ld * 16;
            cp16(doff, g_wph + s);
            cp16(doff + OFF_BL, g_wpl + s);
        }
        cp_commit();
    };

    issue(0, 0);
    cp_wait0();
    __syncthreads();

    for (int kc = 0; kc < 16; ++kc) {
        const int st = kc & 1;
        if (kc < 15) issue(kc + 1, st ^ 1);
        mma_stage(sb + st * STG, fr, C);
        if (kc < 15) cp_wait0();
        __syncthreads();
    }

    // epilogue: stage to smem [c2][r] with bias, then coalesced broadcast x8
    float* Cs = (float*)smem;      // [64][132] floats = 33792 B (fits in 61440)
    const int mw = wid >> 1, nw = wid & 1;
    const int gr = lane >> 2, gc2 = (lane & 3) * 2;
    #pragma unroll
    for (int mi = 0; mi < 2; ++mi) {
        int r = mw * 32 + mi * 16 + gr;
        #pragma unroll
        for (int ni = 0; ni < 4; ++ni) {
            int c2l = nw * 32 + ni * 8 + gc2;
            float b0 = __ldg(bp + c20 + c2l), b1 = __ldg(bp + c20 + c2l + 1);
            Cs[c2l * 132 + r]           = C[mi][ni][0] + b0;
            Cs[(c2l + 1) * 132 + r]     = C[mi][ni][1] + b1;
            Cs[c2l * 132 + r + 8]       = C[mi][ni][2] + b0;
            Cs[(c2l + 1) * 132 + r + 8] = C[mi][ni][3] + b1;
        }
    }
    __syncthreads();

    float* ob = out + (size_t)b * (C_DIM * N_DIM) + (size_t)c20 * N_DIM;
    const int f4 = tid & 31, sub = tid >> 5;
    #pragma unroll 4
    for (int i = 0; i < 64; ++i) {
        int rowid = i * 8 + sub;
        int c2l = rowid >> 3, mrep = rowid & 7;
        float4 v = *(float4*)&Cs[c2l * 132 + f4 * 4];
        *(float4*)(ob + (size_t)c2l * N_DIM + mrep * 128 + f4 * 4) = v;
    }
}

// ---------------------------------------------------------------------------
extern "C" void kernel_launch(void* const* d_in, const int* in_sizes, int n_in,
                              void* d_out, int out_size) {
    const float* x    = (const float*)d_in[0];
    const float* Wqkv = (const float*)d_in[1];
    const float* bqkv = (const float*)d_in[2];
    const float* Wp   = (const float*)d_in[3];
    const float* bp   = (const float*)d_in[4];
    float* out = (float*)d_out;

    cudaFuncSetAttribute(gemm1_mma, cudaFuncAttributeMaxDynamicSharedMemorySize, SMEM_DYN);
    cudaFuncSetAttribute(gemm2_mma, cudaFuncAttributeMaxDynamicSharedMemorySize, SMEM_DYN);

    prep_wv<<<128, 256>>>(Wqkv, bqkv);
    prep_wp<<<dim3(16, 16), dim3(32, 8)>>>(Wp);
    gemm1_mma<<<dim3(8, B_DIM), 256, SMEM_DYN>>>(x);
    gemm2_mma<<<dim3(8, B_DIM), 256, SMEM_DYN>>>(bp, out);
}

// round 5
// speedup vs baseline: 2.7102x; 1.0278x over previous
#include <cuda_runtime.h>
#include <cuda_bf16.h>
#include <cstdint>

#define B_DIM 32
#define C_DIM 512
#define N_DIM 1024   // H*W

// ---------------- device scratch (allocation-free) --------------------------
__device__ __align__(16) unsigned short g_wvh[64 * 512];    // Wv^T hi  [d][c]
__device__ __align__(16) unsigned short g_wvl[64 * 512];    // Wv^T lo
__device__ __align__(16) unsigned short g_wph[512 * 512];   // Wp^T hi  [c2][c]
__device__ __align__(16) unsigned short g_wpl[512 * 512];   // Wp^T lo
__device__ float g_bv[64];
__device__ __align__(16) unsigned g_vh[B_DIM * 1024 * 32];  // v hi bf16 pairs [b][n][d/2]
__device__ __align__(16) unsigned g_vl[B_DIM * 1024 * 32];  // v lo

// ---------------- helpers ----------------------------------------------------
__device__ __forceinline__ unsigned smem_u32(const void* p) {
    unsigned a;
    asm("{ .reg .u64 t; cvta.to.shared.u64 t, %1; cvt.u32.u64 %0, t; }" : "=r"(a) : "l"(p));
    return a;
}
__device__ __forceinline__ void ldm_x4(unsigned* d, unsigned addr) {
    asm volatile("ldmatrix.sync.aligned.m8n8.x4.shared.b16 {%0,%1,%2,%3}, [%4];"
                 : "=r"(d[0]), "=r"(d[1]), "=r"(d[2]), "=r"(d[3]) : "r"(addr));
}
__device__ __forceinline__ void mma_bf16(float* c, const unsigned* a, const unsigned* b) {
    asm volatile(
        "mma.sync.aligned.m16n8k16.row.col.f32.bf16.bf16.f32 "
        "{%0,%1,%2,%3}, {%4,%5,%6,%7}, {%8,%9}, {%0,%1,%2,%3};"
        : "+f"(c[0]), "+f"(c[1]), "+f"(c[2]), "+f"(c[3])
        : "r"(a[0]), "r"(a[1]), "r"(a[2]), "r"(a[3]), "r"(b[0]), "r"(b[1]));
}
__device__ __forceinline__ void cp16(unsigned dst, const void* src) {
    asm volatile("cp.async.cg.shared.global [%0], [%1], 16;" :: "r"(dst), "l"(src));
}
__device__ __forceinline__ void cp_commit() { asm volatile("cp.async.commit_group;" ::: "memory"); }
__device__ __forceinline__ void cp_wait0()  { asm volatile("cp.async.wait_group 0;" ::: "memory"); }
__device__ __forceinline__ void cp_wait1()  { asm volatile("cp.async.wait_group 1;" ::: "memory"); }

// split (f0, f1) into hi/lo bf16x2 (lo half of word = f0)
__device__ __forceinline__ void cvt_split_pair(float f0, float f1, unsigned& h, unsigned& l) {
    asm("cvt.rn.bf16x2.f32 %0, %1, %2;" : "=r"(h) : "f"(f1), "f"(f0));
    float r0 = f0 - __uint_as_float(h << 16);
    float r1 = f1 - __uint_as_float(h & 0xffff0000u);
    asm("cvt.rn.bf16x2.f32 %0, %1, %2;" : "=r"(l) : "f"(r1), "f"(r0));
}

// row pitch: 40 halves = 80 B (ldmatrix conflict-free: 80*i mod 128 distinct)
// ---------------------------------------------------------------------------
// prep kernels
// ---------------------------------------------------------------------------
__global__ void prep_wv(const float* __restrict__ Wqkv, const float* __restrict__ bqkv) {
    int idx = blockIdx.x * blockDim.x + threadIdx.x;   // 32768
    int d = idx & 63, c = idx >> 6;
    const float* p = Wqkv + (size_t)c * 1536 + 1024 + d;
    float s = 0.f;
    #pragma unroll
    for (int h = 0; h < 8; ++h) s += p[h * 64];
    s *= 0.125f;
    __nv_bfloat16 hi = __float2bfloat16(s);
    __nv_bfloat16 lo = __float2bfloat16(s - __bfloat162float(hi));
    g_wvh[d * 512 + c] = *(unsigned short*)&hi;
    g_wvl[d * 512 + c] = *(unsigned short*)&lo;
    if (idx < 64) {
        float t = 0.f;
        #pragma unroll
        for (int h = 0; h < 8; ++h) t += bqkv[1024 + h * 64 + idx];
        g_bv[idx] = t * 0.125f;
    }
}

__global__ void prep_wp(const float* __restrict__ Wp) {
    __shared__ float th[32][33], tl[32][33];
    int tx = threadIdx.x, ty = threadIdx.y;            // (32, 8)
    int c0 = blockIdx.x * 32, c20 = blockIdx.y * 32;
    #pragma unroll
    for (int i = 0; i < 4; ++i) {
        int c = c0 + ty + i * 8;
        float s = Wp[(size_t)c * 512 + c20 + tx];
        float hi = __bfloat162float(__float2bfloat16(s));
        th[ty + i * 8][tx] = hi;
        tl[ty + i * 8][tx] = s - hi;
    }
    __syncthreads();
    #pragma unroll
    for (int i = 0; i < 4; ++i) {
        int c2 = c20 + ty + i * 8;
        __nv_bfloat16 hb = __float2bfloat16(th[tx][ty + i * 8]);
        __nv_bfloat16 lb = __float2bfloat16(tl[tx][ty + i * 8]);
        g_wph[(size_t)c2 * 512 + c0 + tx] = *(unsigned short*)&hb;
        g_wpl[(size_t)c2 * 512 + c0 + tx] = *(unsigned short*)&lb;
    }
}

// ---------------- warp MMA stage (warp tile 32x32, 3 split-passes) ----------
struct Frag { unsigned aoff[2]; unsigned boff[2]; };

__device__ __forceinline__ Frag make_frag(int lane, int mw, int nw, unsigned off_b) {
    Frag fr;
    const int j4 = lane >> 3, r8 = lane & 7;
    #pragma unroll
    for (int mi = 0; mi < 2; ++mi)
        fr.aoff[mi] = ((mw * 32 + mi * 16 + (j4 & 1) * 8 + r8) * 40 + (j4 >> 1) * 8) * 2;
    const int g2 = (lane >> 4) & 1, c8 = (lane >> 3) & 1;
    #pragma unroll
    for (int j2 = 0; j2 < 2; ++j2)
        fr.boff[j2] = off_b + ((nw * 32 + j2 * 16 + g2 * 8 + r8) * 40 + c8 * 8) * 2;
    return fr;
}

template<int AL, int BL>
__device__ __forceinline__ void mma_stage(unsigned base, const Frag& fr, float C[2][4][4]) {
    #pragma unroll
    for (int ks = 0; ks < 2; ++ks) {
        unsigned ah[2][4], al[2][4], bh[2][4], bl[2][4];
        #pragma unroll
        for (int mi = 0; mi < 2; ++mi) {
            ldm_x4(ah[mi], base + fr.aoff[mi] + ks * 32);
            ldm_x4(al[mi], base + fr.aoff[mi] + ks * 32 + AL);
        }
        #pragma unroll
        for (int j2 = 0; j2 < 2; ++j2) {
            ldm_x4(bh[j2], base + fr.boff[j2] + ks * 32);
            ldm_x4(bl[j2], base + fr.boff[j2] + ks * 32 + BL);
        }
        #pragma unroll
        for (int mi = 0; mi < 2; ++mi)
            #pragma unroll
            for (int ni = 0; ni < 4; ++ni) {
                const unsigned* bhp = &bh[ni >> 1][(ni & 1) * 2];
                const unsigned* blp = &bl[ni >> 1][(ni & 1) * 2];
                mma_bf16(C[mi][ni], ah[mi], bhp);
                mma_bf16(C[mi][ni], ah[mi], blp);
                mma_bf16(C[mi][ni], al[mi], bhp);
            }
    }
}

// ---------------------------------------------------------------------------
// GEMM1: tile 256(m=n) x 64(d), 512 thr (16 warps: 8m x 2n), grid (4, 32)
// smem/stage: Ah 256*80=20480 | Al | Bh 64*80=5120 | Bl  -> 51200; 2 stages
// ---------------------------------------------------------------------------
#define G1_AL 20480
#define G1_B  40960
#define G1_BL 5120
#define G1_STG 51200
#define G1_SMEM (2 * G1_STG)

__global__ void __launch_bounds__(512) gemm1_mma(const float* __restrict__ x) {
    extern __shared__ char smem[];
    const int tid = threadIdx.x, lane = tid & 31, wid = tid >> 5;
    const int mw = wid >> 1, nw = wid & 1;
    const int b = blockIdx.y, n0 = blockIdx.x * 256;
    const unsigned sb = smem_u32(smem);
    const Frag fr = make_frag(lane, mw, nw, G1_B);

    const int m_ld = tid & 255, kb0 = tid >> 8;        // A convert: kblock = kb0 + 2i
    const float* xb = x + (size_t)b * (C_DIM * N_DIM) + n0;

    float C[2][4][4] = {};
    float f[2][8];

    auto ldg_chunk = [&](int kc) {
        const float* xc = xb + (size_t)kc * 32 * N_DIM;
        #pragma unroll
        for (int i = 0; i < 2; ++i) {
            int k0 = (kb0 + 2 * i) * 8;
            #pragma unroll
            for (int j = 0; j < 8; ++j)
                f[i][j] = xc[(size_t)(k0 + j) * N_DIM + m_ld];
        }
    };
    auto issueB = [&](int kc, int st) {
        int half = tid >> 8, d = (tid & 255) >> 2, q = tid & 3;
        const unsigned short* src = half ? g_wvl : g_wvh;
        size_t s = (size_t)d * 512 + kc * 32 + q * 8;
        cp16(sb + st * G1_STG + G1_B + half * G1_BL + d * 80 + q * 16, src + s);
        cp_commit();
    };
    auto cvt_sts = [&](int st) {
        char* base = smem + st * G1_STG;
        #pragma unroll
        for (int i = 0; i < 2; ++i) {
            unsigned h[4], l[4];
            #pragma unroll
            for (int p = 0; p < 4; ++p)
                cvt_split_pair(f[i][2 * p], f[i][2 * p + 1], h[p], l[p]);
            unsigned off = m_ld * 80 + (kb0 + 2 * i) * 16;
            *(uint4*)(base + off) = make_uint4(h[0], h[1], h[2], h[3]);
            *(uint4*)(base + G1_AL + off) = make_uint4(l[0], l[1], l[2], l[3]);
        }
    };

    // prologue
    ldg_chunk(0);
    issueB(0, 0);
    cvt_sts(0);
    cp_wait0();
    __syncthreads();

    for (int kc = 0; kc < 16; ++kc) {
        const int st = kc & 1, nst = st ^ 1;
        if (kc < 15) { ldg_chunk(kc + 1); issueB(kc + 1, nst); }
        mma_stage<G1_AL, G1_BL>(sb + st * G1_STG, fr, C);
        if (kc < 15) { cvt_sts(nst); cp_wait0(); }
        __syncthreads();
    }

    // epilogue: add bias, split, store v
    const int gr = lane >> 2, gc2 = (lane & 3) * 2;
    #pragma unroll
    for (int mi = 0; mi < 2; ++mi) {
        int m = n0 + mw * 32 + mi * 16 + gr;
        unsigned base0 = (unsigned)(b * 1024 + m) * 32u;
        unsigned base1 = base0 + 8 * 32;
        #pragma unroll
        for (int ni = 0; ni < 4; ++ni) {
            int d = nw * 32 + ni * 8 + gc2;
            float bv0 = g_bv[d], bv1 = g_bv[d + 1];
            unsigned h, l;
            cvt_split_pair(C[mi][ni][0] + bv0, C[mi][ni][1] + bv1, h, l);
            g_vh[base0 + (d >> 1)] = h;
            g_vl[base0 + (d >> 1)] = l;
            cvt_split_pair(C[mi][ni][2] + bv0, C[mi][ni][3] + bv1, h, l);
            g_vh[base1 + (d >> 1)] = h;
            g_vl[base1 + (d >> 1)] = l;
        }
    }
}

// ---------------------------------------------------------------------------
// GEMM2: tile 128(r) x 128(c2), 512 thr (16 warps: 4m x 4n), grid (4, 32)
// smem/stage: Ah 128*80=10240 | Al | Bh 10240 | Bl -> 40960; 3 stages
// ---------------------------------------------------------------------------
#define G2_AL 10240
#define G2_B  20480
#define G2_BL 10240
#define G2_STG 40960
#define G2_SMEM (3 * G2_STG)

__global__ void __launch_bounds__(512) gemm2_mma(const float* __restrict__ bp,
                                                 float* __restrict__ out) {
    extern __shared__ char smem[];
    const int tid = threadIdx.x, lane = tid & 31, wid = tid >> 5;
    const int mw = wid >> 2, nw = wid & 3;
    const int b = blockIdx.y, c20 = blockIdx.x * 128;
    const unsigned sb = smem_u32(smem);
    const Frag fr = make_frag(lane, mw, nw, G2_B);

    const unsigned short* vhb = (const unsigned short*)g_vh + (size_t)b * 65536;
    const unsigned short* vlb = (const unsigned short*)g_vl + (size_t)b * 65536;

    float C[2][4][4] = {};

    const int r_ld = tid >> 2, q_ld = tid & 3;   // 128 rows x 4 quads
    auto issue = [&](int kc, int st) {
        unsigned stb = sb + st * G2_STG;
        size_t sa = (size_t)r_ld * 512 + kc * 32 + q_ld * 8;
        unsigned da = stb + r_ld * 80 + q_ld * 16;
        cp16(da, vhb + sa);
        cp16(da + G2_AL, vlb + sa);
        size_t sbm = (size_t)(c20 + r_ld) * 512 + kc * 32 + q_ld * 8;
        unsigned db = stb + G2_B + r_ld * 80 + q_ld * 16;
        cp16(db, g_wph + sbm);
        cp16(db + G2_BL, g_wpl + sbm);
        cp_commit();
    };

    issue(0, 0);
    issue(1, 1);

    for (int kc = 0; kc < 16; ++kc) {
        const int st = kc % 3;
        if (kc < 14) cp_wait1(); else cp_wait0();
        __syncthreads();
        if (kc < 14) issue(kc + 2, (kc + 2) % 3);
        mma_stage<G2_AL, G2_BL>(sb + st * G2_STG, fr, C);
    }
    __syncthreads();

    // epilogue: stage to smem [c2][r] with bias, then coalesced x8 broadcast
    float* Cs = (float*)smem;      // [128][132] floats = 67584 B (< 122880)
    const int gr = lane >> 2, gc2 = (lane & 3) * 2;
    #pragma unroll
    for (int mi = 0; mi < 2; ++mi) {
        int r = mw * 32 + mi * 16 + gr;
        #pragma unroll
        for (int ni = 0; ni < 4; ++ni) {
            int c2l = nw * 32 + ni * 8 + gc2;
            float b0 = __ldg(bp + c20 + c2l), b1 = __ldg(bp + c20 + c2l + 1);
            Cs[c2l * 132 + r]           = C[mi][ni][0] + b0;
            Cs[(c2l + 1) * 132 + r]     = C[mi][ni][1] + b1;
            Cs[c2l * 132 + r + 8]       = C[mi][ni][2] + b0;
            Cs[(c2l + 1) * 132 + r + 8] = C[mi][ni][3] + b1;
        }
    }
    __syncthreads();

    float* ob = out + (size_t)b * (C_DIM * N_DIM) + (size_t)c20 * N_DIM;
    const int f4 = tid & 31, sub = tid >> 5;
    #pragma unroll 4
    for (int i = 0; i < 64; ++i) {
        int rowid = i * 16 + sub;               // 1024 row-writes
        int c2l = rowid >> 3, mrep = rowid & 7;
        float4 v = *(float4*)&Cs[c2l * 132 + f4 * 4];
        *(float4*)(ob + (size_t)c2l * N_DIM + mrep * 128 + f4 * 4) = v;
    }
}

// ---------------------------------------------------------------------------
extern "C" void kernel_launch(void* const* d_in, const int* in_sizes, int n_in,
                              void* d_out, int out_size) {
    const float* x    = (const float*)d_in[0];
    const float* Wqkv = (const float*)d_in[1];
    const float* bqkv = (const float*)d_in[2];
    const float* Wp   = (const float*)d_in[3];
    const float* bp   = (const float*)d_in[4];
    float* out = (float*)d_out;

    cudaFuncSetAttribute(gemm1_mma, cudaFuncAttributeMaxDynamicSharedMemorySize, G1_SMEM);
    cudaFuncSetAttribute(gemm2_mma, cudaFuncAttributeMaxDynamicSharedMemorySize, G2_SMEM);

    prep_wv<<<128, 256>>>(Wqkv, bqkv);
    prep_wp<<<dim3(16, 16), dim3(32, 8)>>>(Wp);
    gemm1_mma<<<dim3(4, B_DIM), 512, G1_SMEM>>>(x);
    gemm2_mma<<<dim3(4, B_DIM), 512, G2_SMEM>>>(bp, out);
}

// round 6
// speedup vs baseline: 2.9628x; 1.0932x over previous
#include <cuda_runtime.h>
#include <cuda_bf16.h>
#include <cstdint>

#define B_DIM 32
#define C_DIM 512
#define N_DIM 1024   // H*W

// ---------------- device scratch (allocation-free) --------------------------
__device__ __align__(16) unsigned short g_wvh[64 * 512];    // Wv^T hi  [d][c]
__device__ __align__(16) unsigned short g_wvl[64 * 512];    // Wv^T lo
__device__ __align__(16) unsigned short g_wph[512 * 512];   // Wp^T hi  [c2][c]
__device__ __align__(16) unsigned short g_wpl[512 * 512];   // Wp^T lo
__device__ float g_bv[64];
__device__ __align__(16) unsigned g_vh[B_DIM * 1024 * 32];  // v hi bf16 pairs [b][n][d/2]
__device__ __align__(16) unsigned g_vl[B_DIM * 1024 * 32];  // v lo

// ---------------- helpers ----------------------------------------------------
__device__ __forceinline__ unsigned smem_u32(const void* p) {
    unsigned a;
    asm("{ .reg .u64 t; cvta.to.shared.u64 t, %1; cvt.u32.u64 %0, t; }" : "=r"(a) : "l"(p));
    return a;
}
__device__ __forceinline__ void ldm_x4(unsigned* d, unsigned addr) {
    asm volatile("ldmatrix.sync.aligned.m8n8.x4.shared.b16 {%0,%1,%2,%3}, [%4];"
                 : "=r"(d[0]), "=r"(d[1]), "=r"(d[2]), "=r"(d[3]) : "r"(addr));
}
__device__ __forceinline__ void mma_bf16(float* c, const unsigned* a, const unsigned* b) {
    asm volatile(
        "mma.sync.aligned.m16n8k16.row.col.f32.bf16.bf16.f32 "
        "{%0,%1,%2,%3}, {%4,%5,%6,%7}, {%8,%9}, {%0,%1,%2,%3};"
        : "+f"(c[0]), "+f"(c[1]), "+f"(c[2]), "+f"(c[3])
        : "r"(a[0]), "r"(a[1]), "r"(a[2]), "r"(a[3]), "r"(b[0]), "r"(b[1]));
}
__device__ __forceinline__ void cp16(unsigned dst, const void* src) {
    asm volatile("cp.async.cg.shared.global [%0], [%1], 16;" :: "r"(dst), "l"(src));
}
__device__ __forceinline__ void cp_commit() { asm volatile("cp.async.commit_group;" ::: "memory"); }
__device__ __forceinline__ void cp_wait0()  { asm volatile("cp.async.wait_group 0;" ::: "memory"); }

__device__ __forceinline__ void cvt_split_pair(float f0, float f1, unsigned& h, unsigned& l) {
    asm("cvt.rn.bf16x2.f32 %0, %1, %2;" : "=r"(h) : "f"(f1), "f"(f0));
    float r0 = f0 - __uint_as_float(h << 16);
    float r1 = f1 - __uint_as_float(h & 0xffff0000u);
    asm("cvt.rn.bf16x2.f32 %0, %1, %2;" : "=r"(l) : "f"(r1), "f"(r0));
}

// ---------------------------------------------------------------------------
// prep (single launch): blocks [0,128) -> Wv^T split + bias; [128,384) -> Wp^T
// ---------------------------------------------------------------------------
__global__ void prep_all(const float* __restrict__ Wqkv, const float* __restrict__ bqkv,
                         const float* __restrict__ Wp) {
    int bid = blockIdx.x, tid = threadIdx.x;
    if (bid < 128) {
        int idx = bid * 256 + tid;                 // 32768
        int d = idx & 63, c = idx >> 6;
        const float* p = Wqkv + (size_t)c * 1536 + 1024 + d;
        float s = 0.f;
        #pragma unroll
        for (int h = 0; h < 8; ++h) s += p[h * 64];
        s *= 0.125f;
        __nv_bfloat16 hi = __float2bfloat16(s);
        __nv_bfloat16 lo = __float2bfloat16(s - __bfloat162float(hi));
        g_wvh[d * 512 + c] = *(unsigned short*)&hi;
        g_wvl[d * 512 + c] = *(unsigned short*)&lo;
        if (idx < 64) {
            float t = 0.f;
            #pragma unroll
            for (int h = 0; h < 8; ++h) t += bqkv[1024 + h * 64 + idx];
            g_bv[idx] = t * 0.125f;
        }
    } else {
        __shared__ float th[32][33], tl[32][33];
        int t = bid - 128;                          // 256 tiles
        int c0 = (t & 15) * 32, c20 = (t >> 4) * 32;
        int tx = tid & 31, ty = tid >> 5;           // (32, 8)
        #pragma unroll
        for (int i = 0; i < 4; ++i) {
            int c = c0 + ty + i * 8;
            float s = Wp[(size_t)c * 512 + c20 + tx];
            float hi = __bfloat162float(__float2bfloat16(s));
            th[ty + i * 8][tx] = hi;
            tl[ty + i * 8][tx] = s - hi;
        }
        __syncthreads();
        #pragma unroll
        for (int i = 0; i < 4; ++i) {
            int c2 = c20 + ty + i * 8;
            __nv_bfloat16 hb = __float2bfloat16(th[tx][ty + i * 8]);
            __nv_bfloat16 lb = __float2bfloat16(tl[tx][ty + i * 8]);
            g_wph[(size_t)c2 * 512 + c0 + tx] = *(unsigned short*)&hb;
            g_wpl[(size_t)c2 * 512 + c0 + tx] = *(unsigned short*)&lb;
        }
    }
}

// ---------------- warp MMA stage -------------------------------------------
struct Frag { unsigned aoff[2]; unsigned boff[2]; };

// PITCHB = row pitch in bytes
template<int PITCHB>
__device__ __forceinline__ Frag make_frag(int lane, int mw, int nw, unsigned off_b) {
    Frag fr;
    const int j4 = lane >> 3, r8 = lane & 7;
    #pragma unroll
    for (int mi = 0; mi < 2; ++mi)
        fr.aoff[mi] = (mw * 32 + mi * 16 + (j4 & 1) * 8 + r8) * PITCHB + (j4 >> 1) * 16;
    const int g2 = (lane >> 4) & 1, c8 = (lane >> 3) & 1;
    #pragma unroll
    for (int j2 = 0; j2 < 2; ++j2)
        fr.boff[j2] = off_b + (nw * 32 + j2 * 16 + g2 * 8 + r8) * PITCHB + c8 * 16;
    return fr;
}

template<int KS, int AL, int BL>
__device__ __forceinline__ void mma_stage(unsigned base, const Frag& fr, float C[2][4][4]) {
    #pragma unroll
    for (int ks = 0; ks < KS; ++ks) {
        unsigned ah[2][4], al[2][4], bh[2][4], bl[2][4];
        #pragma unroll
        for (int mi = 0; mi < 2; ++mi) {
            ldm_x4(ah[mi], base + fr.aoff[mi] + ks * 32);
            ldm_x4(al[mi], base + fr.aoff[mi] + ks * 32 + AL);
        }
        #pragma unroll
        for (int j2 = 0; j2 < 2; ++j2) {
            ldm_x4(bh[j2], base + fr.boff[j2] + ks * 32);
            ldm_x4(bl[j2], base + fr.boff[j2] + ks * 32 + BL);
        }
        #pragma unroll
        for (int mi = 0; mi < 2; ++mi)
            #pragma unroll
            for (int ni = 0; ni < 4; ++ni) {
                const unsigned* bhp = &bh[ni >> 1][(ni & 1) * 2];
                const unsigned* blp = &bl[ni >> 1][(ni & 1) * 2];
                mma_bf16(C[mi][ni], ah[mi], bhp);
                mma_bf16(C[mi][ni], ah[mi], blp);
                mma_bf16(C[mi][ni], al[mi], bhp);
            }
    }
}

// ---------------------------------------------------------------------------
// GEMM1: tile 256(n) x 64(d), 512 thr (16 warps: 8m x 2n), K-chunk 32, 16 chunks
// 2 stages, pre-MMA STS. pitch 80B.
// stage: Ah 256*80=20480 | Al | Bh 64*80=5120 | Bl -> 51200
// ---------------------------------------------------------------------------
#define G1_AL 20480
#define G1_B  40960
#define G1_BL 5120
#define G1_STG 51200
#define G1_SMEM (2 * G1_STG)

__global__ void __launch_bounds__(512) gemm1_mma(const float* __restrict__ x) {
    extern __shared__ char smem[];
    const int tid = threadIdx.x, lane = tid & 31, wid = tid >> 5;
    const int mw = wid >> 1, nw = wid & 1;
    const int b = blockIdx.y, n0 = blockIdx.x * 256;
    const unsigned sb = smem_u32(smem);
    const Frag fr = make_frag<80>(lane, mw, nw, G1_B);

    const int m_ld = tid & 255, kb0 = tid >> 8;        // A convert: kblock = kb0 + 2i
    const float* xb = x + (size_t)b * (C_DIM * N_DIM) + n0;

    float C[2][4][4] = {};
    float f[2][8];

    auto ldg_chunk = [&](int kc) {
        const float* xc = xb + (size_t)kc * 32 * N_DIM;
        #pragma unroll
        for (int i = 0; i < 2; ++i) {
            int k0 = (kb0 + 2 * i) * 8;
            #pragma unroll
            for (int j = 0; j < 8; ++j)
                f[i][j] = xc[(size_t)(k0 + j) * N_DIM + m_ld];
        }
    };
    auto issueB = [&](int kc, int st) {
        int half = tid >> 8, d = (tid & 255) >> 2, q = tid & 3;
        const unsigned short* src = half ? g_wvl : g_wvh;
        size_t s = (size_t)d * 512 + kc * 32 + q * 8;
        cp16(sb + st * G1_STG + G1_B + half * G1_BL + d * 80 + q * 16, src + s);
        cp_commit();
    };
    auto cvt_sts = [&](int st) {
        char* base = smem + st * G1_STG;
        #pragma unroll
        for (int i = 0; i < 2; ++i) {
            unsigned h[4], l[4];
            #pragma unroll
            for (int p = 0; p < 4; ++p)
                cvt_split_pair(f[i][2 * p], f[i][2 * p + 1], h[p], l[p]);
            unsigned off = m_ld * 80 + (kb0 + 2 * i) * 16;
            *(uint4*)(base + off) = make_uint4(h[0], h[1], h[2], h[3]);
            *(uint4*)(base + G1_AL + off) = make_uint4(l[0], l[1], l[2], l[3]);
        }
    };

    // prologue: chunk 0 staged, chunk 1 in registers
    ldg_chunk(0);
    issueB(0, 0);
    cvt_sts(0);
    ldg_chunk(1);

    for (int kc = 0; kc < 16; ++kc) {
        const int st = kc & 1, nst = st ^ 1;
        cp_wait0();
        __syncthreads();
        if (kc < 15) { cvt_sts(nst); issueB(kc + 1, nst); }
        if (kc < 14) ldg_chunk(kc + 2);
        mma_stage<2, G1_AL, G1_BL>(sb + st * G1_STG, fr, C);
    }

    // epilogue: add bias, split, store v
    const int gr = lane >> 2, gc2 = (lane & 3) * 2;
    #pragma unroll
    for (int mi = 0; mi < 2; ++mi) {
        int m = n0 + mw * 32 + mi * 16 + gr;
        unsigned base0 = (unsigned)(b * 1024 + m) * 32u;
        unsigned base1 = base0 + 8 * 32;
        #pragma unroll
        for (int ni = 0; ni < 4; ++ni) {
            int d = nw * 32 + ni * 8 + gc2;
            float bv0 = g_bv[d], bv1 = g_bv[d + 1];
            unsigned h, l;
            cvt_split_pair(C[mi][ni][0] + bv0, C[mi][ni][1] + bv1, h, l);
            g_vh[base0 + (d >> 1)] = h;
            g_vl[base0 + (d >> 1)] = l;
            cvt_split_pair(C[mi][ni][2] + bv0, C[mi][ni][3] + bv1, h, l);
            g_vh[base1 + (d >> 1)] = h;
            g_vl[base1 + (d >> 1)] = l;
        }
    }
}

// ---------------------------------------------------------------------------
// GEMM2: tile 128(r) x 128(c2), 512 thr (16 warps: 4m x 4n), K-chunk 64, 8 chunks
// 2 stages, pitch 144B. stage: Ah 128*144=18432 | Al | Bh | Bl -> 73728
// ---------------------------------------------------------------------------
#define G2_AL 18432
#define G2_B  36864
#define G2_BL 18432
#define G2_STG 73728
#define G2_SMEM (2 * G2_STG)

__global__ void __launch_bounds__(512) gemm2_mma(const float* __restrict__ bp,
                                                 float* __restrict__ out) {
    extern __shared__ char smem[];
    const int tid = threadIdx.x, lane = tid & 31, wid = tid >> 5;
    const int mw = wid >> 2, nw = wid & 3;
    const int b = blockIdx.y, c20 = blockIdx.x * 128;
    const unsigned sb = smem_u32(smem);
    const Frag fr = make_frag<144>(lane, mw, nw, G2_B);

    const unsigned short* vhb = (const unsigned short*)g_vh + (size_t)b * 65536;
    const unsigned short* vlb = (const unsigned short*)g_vl + (size_t)b * 65536;

    float C[2][4][4] = {};

    auto issue = [&](int kc, int st) {
        unsigned stb = sb + st * G2_STG;
        #pragma unroll
        for (int i = 0; i < 2; ++i) {
            int idx = tid * 2 + i;                 // 0..1023
            int r = idx >> 3, q = idx & 7;
            size_t s = (size_t)r * 512 + kc * 64 + q * 8;
            unsigned off = r * 144 + q * 16;
            cp16(stb + off, vhb + s);
            cp16(stb + off + G2_AL, vlb + s);
            size_t sB = (size_t)(c20 + r) * 512 + kc * 64 + q * 8;
            cp16(stb + G2_B + off, g_wph + sB);
            cp16(stb + G2_B + off + G2_BL, g_wpl + sB);
        }
        cp_commit();
    };

    issue(0, 0);

    for (int kc = 0; kc < 8; ++kc) {
        const int st = kc & 1;
        cp_wait0();
        __syncthreads();
        if (kc < 7) issue(kc + 1, st ^ 1);
        mma_stage<4, G2_AL, G2_BL>(sb + st * G2_STG, fr, C);
    }
    __syncthreads();

    // epilogue: stage to smem [c2][r] with bias, then coalesced x8 broadcast
    float* Cs = (float*)smem;      // [128][132] floats = 67584 B (< 147456)
    const int gr = lane >> 2, gc2 = (lane & 3) * 2;
    #pragma unroll
    for (int mi = 0; mi < 2; ++mi) {
        int r = mw * 32 + mi * 16 + gr;
        #pragma unroll
        for (int ni = 0; ni < 4; ++ni) {
            int c2l = nw * 32 + ni * 8 + gc2;
            float b0 = __ldg(bp + c20 + c2l), b1 = __ldg(bp + c20 + c2l + 1);
            Cs[c2l * 132 + r]           = C[mi][ni][0] + b0;
            Cs[(c2l + 1) * 132 + r]     = C[mi][ni][1] + b1;
            Cs[c2l * 132 + r + 8]       = C[mi][ni][2] + b0;
            Cs[(c2l + 1) * 132 + r + 8] = C[mi][ni][3] + b1;
        }
    }
    __syncthreads();

    float* ob = out + (size_t)b * (C_DIM * N_DIM) + (size_t)c20 * N_DIM;
    const int f4 = tid & 31, sub = tid >> 5;
    #pragma unroll 4
    for (int i = 0; i < 64; ++i) {
        int rowid = i * 16 + sub;               // 1024 row-writes
        int c2l = rowid >> 3, mrep = rowid & 7;
        float4 v = *(float4*)&Cs[c2l * 132 + f4 * 4];
        *(float4*)(ob + (size_t)c2l * N_DIM + mrep * 128 + f4 * 4) = v;
    }
}

// ---------------------------------------------------------------------------
extern "C" void kernel_launch(void* const* d_in, const int* in_sizes, int n_in,
                              void* d_out, int out_size) {
    const float* x    = (const float*)d_in[0];
    const float* Wqkv = (const float*)d_in[1];
    const float* bqkv = (const float*)d_in[2];
    const float* Wp   = (const float*)d_in[3];
    const float* bp   = (const float*)d_in[4];
    float* out = (float*)d_out;

    cudaFuncSetAttribute(gemm1_mma, cudaFuncAttributeMaxDynamicSharedMemorySize, G1_SMEM);
    cudaFuncSetAttribute(gemm2_mma, cudaFuncAttributeMaxDynamicSharedMemorySize, G2_SMEM);

    prep_all<<<384, 256>>>(Wqkv, bqkv, Wp);
    gemm1_mma<<<dim3(4, B_DIM), 512, G1_SMEM>>>(x);
    gemm2_mma<<<dim3(4, B_DIM), 512, G2_SMEM>>>(bp, out);
}